// round 5
// baseline (speedup 1.0000x reference)
#include <cuda_runtime.h>
#include <cuda_bf16.h>

// MLPAttention: B=4, N=512, KLEN=512, D=64, TAU=4
//   Wq=W1[0::2], Wk=W1[1::2]; hq=Q@Wq+b1; hk=K@Wk
//   res[n,k] = sum_e relu(hq[n,e]+hk[k,e])*W2[e]   (b2 cancels in softmax)
//   relu(x)*w = 0.5*w*(x+|x|); packed f32x2 over e-pairs, horizontal add at end.
//   att = softmax(res/TAU); out = att@V
// Outputs: out (B*N*D) then att (B*N*K).

#define BB 4
#define NN 512
#define KL 512
#define DD 64

typedef unsigned long long ull;

// hk e-paired: float2 [b][e/2][k] = {hk[2ep][k], hk[2ep+1][k]}
__device__ float2 g_hkT2[BB * (DD / 2) * KL];

__device__ __forceinline__ ull pk2(float x, float y) {
    ull r; asm("mov.b64 %0, {%1, %2};" : "=l"(r) : "f"(x), "f"(y)); return r;
}
__device__ __forceinline__ float2 up2(ull u) {
    float2 f; asm("mov.b64 {%0, %1}, %2;" : "=f"(f.x), "=f"(f.y) : "l"(u)); return f;
}
__device__ __forceinline__ ull fadd2(ull a, ull b) {
    ull r; asm("add.rn.f32x2 %0, %1, %2;" : "=l"(r) : "l"(a), "l"(b)); return r;
}
__device__ __forceinline__ ull ffma2(ull a, ull b, ull c) {
    ull r; asm("fma.rn.f32x2 %0, %1, %2, %3;" : "=l"(r) : "l"(a), "l"(b), "l"(c)); return r;
}

// ---------- Kernel A: hkT2 = (K@Wk)^T, e-paired ----------
// grid 128: b(4) x kt(8) x qt(4). 256 threads: k=t&63, ei=t>>6 (4 e each).
__global__ __launch_bounds__(256) void kA(const float* __restrict__ K,
                                          const float* __restrict__ W1,
                                          float2* __restrict__ hkT2) {
    __shared__ float Ks[64 * 65];
    __shared__ float Ws[64 * 16];   // [d][eq]
    int bid = blockIdx.x;
    int b  = bid >> 5;
    int kt = (bid >> 2) & 7;
    int qt = bid & 3;
    int t = threadIdx.x;

#pragma unroll
    for (int j = 0; j < 16; j++) {
        int idx = t + 256 * j;
        int kk = idx >> 6, d = idx & 63;
        Ks[kk * 65 + d] = K[(b * 512 + kt * 64 + kk) * 64 + d];
    }
#pragma unroll
    for (int j = 0; j < 4; j++) {
        int idx = t + 256 * j;
        int d = idx >> 4, eq = idx & 15;
        Ws[idx] = W1[d * 128 + 64 + qt * 16 + eq];   // W1[2d+1][qt*16+eq]
    }
    __syncthreads();

    int k = t & 63, ei = t >> 6;
    float a0 = 0.f, a1 = 0.f, a2 = 0.f, a3 = 0.f;
#pragma unroll
    for (int d = 0; d < 64; d++) {
        float kv = Ks[k * 65 + d];
        float4 wv = *(const float4*)&Ws[d * 16 + ei * 4];
        a0 = fmaf(kv, wv.x, a0);
        a1 = fmaf(kv, wv.y, a1);
        a2 = fmaf(kv, wv.z, a2);
        a3 = fmaf(kv, wv.w, a3);
    }
    int e0 = qt * 16 + ei * 4;
    int base = b * (32 * 512) + kt * 64 + k;
    hkT2[base + (e0 >> 1) * 512]       = make_float2(a0, a1);
    hkT2[base + ((e0 >> 1) + 1) * 512] = make_float2(a2, a3);
}

// ---------- Kernel BC: hq -> res -> softmax -> att, out = att@V ----------
// grid 256 (b x 64 n-tiles of 8 rows), 256 threads, 3 blocks/SM.
// Each thread: 2 k-columns (t, t+256). S lifecycle:
//   Qs[8][64] (phase0, first 2KB) -> res[8][512] -> att2 ull[4 rp][512] -> red ull[4][256]
__global__ __launch_bounds__(256, 3) void kBC(const float* __restrict__ Q,
                                              const float* __restrict__ W1,
                                              const float* __restrict__ b1,
                                              const float2* __restrict__ hkT2,
                                              const float* __restrict__ W2,
                                              const float* __restrict__ V,
                                              float* __restrict__ att,
                                              float* __restrict__ out) {
    __shared__ __align__(16) float S[4096];
    __shared__ __align__(16) float hq_p[512];   // [ep][row][par] : ep*16 + row*2 + par
    __shared__ ull w2ps[32];                    // {0.5*w2[2ep], 0.5*w2[2ep+1]}

    int b  = blockIdx.x >> 6;
    int n0 = (blockIdx.x & 63) << 3;
    int t  = threadIdx.x;

    // ---- phase 0: stage Q, compute hq (2 outputs per thread) ----
#pragma unroll
    for (int j = 0; j < 2; j++) {
        int idx = t + 256 * j;
        int row = idx >> 6, e = idx & 63;
        S[idx] = Q[(b * 512 + n0 + row) * 64 + e];
    }
    if (t < 32) {
        float2 w = *(const float2*)&W2[2 * t];
        w2ps[t] = pk2(0.5f * w.x, 0.5f * w.y);
    }
    __syncthreads();
#pragma unroll
    for (int j = 0; j < 2; j++) {
        int idx = t + 256 * j;
        int row = idx >> 6, e = idx & 63;
        float a = __ldg(&b1[e]);
        const float* qrow = S + row * 64;
#pragma unroll
        for (int d = 0; d < 64; d++)
            a = fmaf(qrow[d], __ldg(&W1[d * 128 + e]), a);  // W1[2d][e], L1-hot
        hq_p[(e >> 1) * 16 + row * 2 + (e & 1)] = a;
    }
    __syncthreads();

    // ---- phase 1: res[8 rows][k=t, k=t+256], packed over e-pairs ----
    const float2* hkA = hkT2 + b * (32 * 512) + t;           // k = t
    const ulonglong2* hq22 = (const ulonglong2*)hq_p;        // [ep][4] rows{01,23,45,67}

    ull aA0=0,aA1=0,aA2=0,aA3=0,aA4=0,aA5=0,aA6=0,aA7=0;     // k = t
    ull aB0=0,aB1=0,aB2=0,aB3=0,aB4=0,aB5=0,aB6=0,aB7=0;     // k = t+256
#pragma unroll 4
    for (int ep = 0; ep < 32; ep++) {
        float2 hA = __ldg(hkA + ep * 512);        // coalesced LDG.64, L2-resident
        float2 hB = __ldg(hkA + ep * 512 + 256);
        ull hpA = pk2(hA.x, hA.y);
        ull hpB = pk2(hB.x, hB.y);
        ull w2p = w2ps[ep];
        ulonglong2 h01 = hq22[ep * 4 + 0];        // broadcast LDS.128 (shared by both k)
        ulonglong2 h23 = hq22[ep * 4 + 1];
        ulonglong2 h45 = hq22[ep * 4 + 2];
        ulonglong2 h67 = hq22[ep * 4 + 3];
#define RSTEP(A, H, HK) { ull s_ = fadd2((H), (HK)); \
                          ull u_ = fadd2(s_, s_ & 0x7fffffff7fffffffULL); \
                          (A) = ffma2(u_, w2p, (A)); }
        RSTEP(aA0, h01.x, hpA) RSTEP(aA1, h01.y, hpA)
        RSTEP(aA2, h23.x, hpA) RSTEP(aA3, h23.y, hpA)
        RSTEP(aA4, h45.x, hpA) RSTEP(aA5, h45.y, hpA)
        RSTEP(aA6, h67.x, hpA) RSTEP(aA7, h67.y, hpA)
        RSTEP(aB0, h01.x, hpB) RSTEP(aB1, h01.y, hpB)
        RSTEP(aB2, h23.x, hpB) RSTEP(aB3, h23.y, hpB)
        RSTEP(aB4, h45.x, hpB) RSTEP(aB5, h45.y, hpB)
        RSTEP(aB6, h67.x, hpB) RSTEP(aB7, h67.y, hpB)
#undef RSTEP
    }
    {   // horizontal add (even-e + odd-e), stage res
        float2 x;
        x = up2(aA0); S[0*512 + t] = x.x + x.y;  x = up2(aB0); S[0*512 + t + 256] = x.x + x.y;
        x = up2(aA1); S[1*512 + t] = x.x + x.y;  x = up2(aB1); S[1*512 + t + 256] = x.x + x.y;
        x = up2(aA2); S[2*512 + t] = x.x + x.y;  x = up2(aB2); S[2*512 + t + 256] = x.x + x.y;
        x = up2(aA3); S[3*512 + t] = x.x + x.y;  x = up2(aB3); S[3*512 + t + 256] = x.x + x.y;
        x = up2(aA4); S[4*512 + t] = x.x + x.y;  x = up2(aB4); S[4*512 + t + 256] = x.x + x.y;
        x = up2(aA5); S[5*512 + t] = x.x + x.y;  x = up2(aB5); S[5*512 + t + 256] = x.x + x.y;
        x = up2(aA6); S[6*512 + t] = x.x + x.y;  x = up2(aB6); S[6*512 + t + 256] = x.x + x.y;
        x = up2(aA7); S[7*512 + t] = x.x + x.y;  x = up2(aB7); S[7*512 + t + 256] = x.x + x.y;
    }
    __syncthreads();

    // ---- phase 2: softmax, warp w (0..7) owns row n0+w ----
    int w = t >> 5, lane = t & 31;
    float v[16];
    float m = -1e30f;
#pragma unroll
    for (int i = 0; i < 16; i++) {
        v[i] = S[w * 512 + lane + 32 * i];
        m = fmaxf(m, v[i]);
    }
#pragma unroll
    for (int o = 16; o; o >>= 1) m = fmaxf(m, __shfl_xor_sync(0xffffffffu, m, o));
    float sum = 0.f;
#pragma unroll
    for (int i = 0; i < 16; i++) {
        v[i] = __expf((v[i] - m) * 0.25f);   // /TAU
        sum += v[i];
    }
#pragma unroll
    for (int o = 16; o; o >>= 1) sum += __shfl_xor_sync(0xffffffffu, sum, o);
    float inv = 1.f / sum;
    __syncthreads();   // res reads done -> S becomes att2

    {   // write att (gmem) + att2 (smem, ull[rowpair][k])
        float* ap = att + (b * 512 + n0 + w) * 512 + lane;
        int base = (w >> 1) * 1024 + (w & 1);
#pragma unroll
        for (int i = 0; i < 16; i++) {
            float av = v[i] * inv;
            ap[32 * i] = av;
            S[base + 2 * (lane + 32 * i)] = av;
        }
    }
    __syncthreads();

    // ---- phase 3: out = att @ V (split-k, 4 chunks of 128) ----
    int split = t >> 6, r6 = t & 63, rp2 = r6 >> 5, d2 = r6 & 31;
    const float2* Vb = (const float2*)V + (size_t)b * 512 * 32 + d2;
    const ull* A2 = (const ull*)S;               // [rowpair][k]
    ull o0 = 0, o1 = 0, o2 = 0, o3 = 0;
    int k0 = split * 128;
#pragma unroll 8
    for (int kk = 0; kk < 128; kk++) {
        int k = k0 + kk;
        float2 vv = __ldg(Vb + k * 32);          // coalesced LDG.64, L2-hot
        ull vx = pk2(vv.x, vv.x);
        ull vy = pk2(vv.y, vv.y);
        ull a0 = A2[(2 * rp2) * 512 + k];        // broadcast LDS.64
        ull a1 = A2[(2 * rp2 + 1) * 512 + k];
        o0 = ffma2(a0, vx, o0);                  // rows {4rp2,4rp2+1}, col 2d2
        o1 = ffma2(a0, vy, o1);                  //                    col 2d2+1
        o2 = ffma2(a1, vx, o2);                  // rows {4rp2+2,4rp2+3}
        o3 = ffma2(a1, vy, o3);
    }
    __syncthreads();   // att2 reads done -> S becomes reduction buffer

    ull* red = (ull*)S;                          // [split 4][256]
    {
        int id0 = (2 * rp2) * 64 + 2 * d2;
        int id1 = (2 * rp2 + 1) * 64 + 2 * d2;
        red[split * 256 + id0]     = o0;
        red[split * 256 + id0 + 1] = o1;
        red[split * 256 + id1]     = o2;
        red[split * 256 + id1 + 1] = o3;
    }
    __syncthreads();

    {   // every thread reduces one float2 output over 4 splits
        ull r = fadd2(fadd2(red[t], red[256 + t]),
                      fadd2(red[512 + t], red[768 + t]));
        float2 rv = up2(r);
        int rp = t >> 6, c = t & 63;
        int nrow = b * 512 + n0 + 2 * rp;
        out[nrow * 64 + c]       = rv.x;
        out[(nrow + 1) * 64 + c] = rv.y;
    }
}

extern "C" void kernel_launch(void* const* d_in, const int* in_sizes, int n_in,
                              void* d_out, int out_size) {
    const float* Q  = (const float*)d_in[0];
    const float* K  = (const float*)d_in[1];
    const float* V  = (const float*)d_in[2];
    const float* W1 = (const float*)d_in[3];
    const float* b1 = (const float*)d_in[4];
    const float* W2 = (const float*)d_in[5];
    // b2 cancels in softmax

    float* out = (float*)d_out;                   // B*N*D
    float* att = (float*)d_out + BB * NN * DD;    // B*N*KL

    float2* hkT2; cudaGetSymbolAddress((void**)&hkT2, g_hkT2);

    kA<<<128, 256>>>(K, W1, hkT2);
    kBC<<<256, 256>>>(Q, W1, b1, hkT2, W2, V, att, out);
}